// round 1
// baseline (speedup 1.0000x reference)
#include <cuda_runtime.h>
#include <math.h>

#define TT 1024
#define HH 2048
#define EE 16
#define KTOP 4
#define II 1408
#define ISH 2816

// ---- scratch (device globals; every element rewritten each launch) ----
__device__ float g_act[TT * KTOP * II];      // routed activations (silu(g)*u*w), indexed [code*II + i], code = t*4+slot
__device__ float g_downbuf[TT * KTOP * HH];  // per-(token,slot) down-proj partials
__device__ float g_shact[(size_t)TT * ISH];  // shared expert activations
__device__ float g_shdown[TT * HH];          // shared expert down output
__device__ int   g_counts[EE];
__device__ int   g_list[EE * TT];            // per-expert list of codes (t*4+slot)
__device__ float g_tw[TT * KTOP];            // normalized top-k weights, indexed by code

__global__ void zero_counts_kernel() {
    if (threadIdx.x < EE) g_counts[threadIdx.x] = 0;
}

// ---------------- router: logits -> softmax -> top4 -> renorm -> lists ----------------
__global__ void router_kernel(const float* __restrict__ x, const float* __restrict__ gw) {
    int t = blockIdx.x * 4 + (threadIdx.x >> 5);
    int lane = threadIdx.x & 31;
    if (t >= TT) return;
    float acc[EE];
#pragma unroll
    for (int e = 0; e < EE; e++) acc[e] = 0.f;
    const float* xr = x + (size_t)t * HH;
    for (int h = lane; h < HH; h += 32) {
        float xv = xr[h];
#pragma unroll
        for (int e = 0; e < EE; e++) acc[e] += xv * gw[e * HH + h];
    }
#pragma unroll
    for (int e = 0; e < EE; e++) {
#pragma unroll
        for (int o = 16; o > 0; o >>= 1) acc[e] += __shfl_xor_sync(0xffffffffu, acc[e], o);
    }
    if (lane == 0) {
        float m = acc[0];
#pragma unroll
        for (int e = 1; e < EE; e++) m = fmaxf(m, acc[e]);
        float sc[EE];
        float s = 0.f;
#pragma unroll
        for (int e = 0; e < EE; e++) { sc[e] = expf(acc[e] - m); s += sc[e]; }
        float inv = 1.f / s;
#pragma unroll
        for (int e = 0; e < EE; e++) sc[e] *= inv;
        int idx[KTOP]; float w[KTOP]; float wsum = 0.f;
#pragma unroll
        for (int k = 0; k < KTOP; k++) {
            int bi = 0; float bv = -1.f;
#pragma unroll
            for (int e = 0; e < EE; e++) if (sc[e] > bv) { bv = sc[e]; bi = e; }
            idx[k] = bi; w[k] = bv; sc[bi] = -2.f; wsum += bv;
        }
        float winv = 1.f / wsum;
        for (int k = 0; k < KTOP; k++) {
            int code = t * KTOP + k;
            g_tw[code] = w[k] * winv;
            int e = idx[k];
            int pos = atomicAdd(&g_counts[e], 1);
            g_list[e * TT + pos] = code;
        }
    }
}

// ---------------- routed experts: fused gate+up gather-GEMM (64x64x16 tiles) ----------------
// grid: (II/64, TT/64, EE); block 256
__global__ void __launch_bounds__(256) gateup_kernel(const float* __restrict__ x,
                                                     const float* __restrict__ wgA,
                                                     const float* __restrict__ wuA) {
    int e = blockIdx.z;
    int cnt = g_counts[e];
    int row0 = blockIdx.y * 64;
    if (row0 >= cnt) return;
    int n0 = blockIdx.x * 64;

    __shared__ float As[16][68];
    __shared__ float Bg[16][64];
    __shared__ float Bu[16][64];
    __shared__ int codes[64];

    int tid = threadIdx.x;
    if (tid < 64) {
        int r = row0 + tid;
        codes[tid] = (r < cnt) ? g_list[e * TT + r] : 0;
    }
    __syncthreads();

    const float* wgb = wgA + (size_t)e * HH * II;
    const float* wub = wuA + (size_t)e * HH * II;

    int ar = tid >> 2, aseg = tid & 3;
    int atok = codes[ar] >> 2;
    int br = tid >> 4, bc = (tid & 15) * 4;
    int tx = tid & 15, ty = tid >> 4;

    float cg[4][4], cu[4][4];
#pragma unroll
    for (int i = 0; i < 4; i++)
#pragma unroll
        for (int j = 0; j < 4; j++) { cg[i][j] = 0.f; cu[i][j] = 0.f; }

    for (int k0 = 0; k0 < HH; k0 += 16) {
        float4 av = *(const float4*)(x + (size_t)atok * HH + k0 + aseg * 4);
        As[aseg * 4 + 0][ar] = av.x;
        As[aseg * 4 + 1][ar] = av.y;
        As[aseg * 4 + 2][ar] = av.z;
        As[aseg * 4 + 3][ar] = av.w;
        *(float4*)&Bg[br][bc] = *(const float4*)(wgb + (size_t)(k0 + br) * II + n0 + bc);
        *(float4*)&Bu[br][bc] = *(const float4*)(wub + (size_t)(k0 + br) * II + n0 + bc);
        __syncthreads();
#pragma unroll
        for (int k = 0; k < 16; k++) {
            float4 a4 = *(float4*)&As[k][ty * 4];
            float4 g4 = *(float4*)&Bg[k][tx * 4];
            float4 u4 = *(float4*)&Bu[k][tx * 4];
            float a[4] = {a4.x, a4.y, a4.z, a4.w};
            float bg[4] = {g4.x, g4.y, g4.z, g4.w};
            float bu[4] = {u4.x, u4.y, u4.z, u4.w};
#pragma unroll
            for (int mi = 0; mi < 4; mi++)
#pragma unroll
                for (int ni = 0; ni < 4; ni++) {
                    cg[mi][ni] += a[mi] * bg[ni];
                    cu[mi][ni] += a[mi] * bu[ni];
                }
        }
        __syncthreads();
    }

#pragma unroll
    for (int mi = 0; mi < 4; mi++) {
        int r = row0 + ty * 4 + mi;
        if (r >= cnt) continue;
        int code = codes[ty * 4 + mi];
        float wt = g_tw[code];
        float* outp = g_act + (size_t)code * II + n0 + tx * 4;
#pragma unroll
        for (int ni = 0; ni < 4; ni++) {
            float gv = cg[mi][ni];
            float a = (gv / (1.f + __expf(-gv))) * cu[mi][ni] * wt;
            outp[ni] = a;
        }
    }
}

// ---------------- routed down-proj gather-GEMM ----------------
// grid: (HH/64, TT/64, EE); block 256
__global__ void __launch_bounds__(256) down_kernel(const float* __restrict__ wdA) {
    int e = blockIdx.z;
    int cnt = g_counts[e];
    int row0 = blockIdx.y * 64;
    if (row0 >= cnt) return;
    int n0 = blockIdx.x * 64;

    __shared__ float As[16][68];
    __shared__ float Bs[16][64];
    __shared__ int codes[64];

    int tid = threadIdx.x;
    if (tid < 64) {
        int r = row0 + tid;
        codes[tid] = (r < cnt) ? g_list[e * TT + r] : 0;
    }
    __syncthreads();

    const float* wb = wdA + (size_t)e * II * HH;
    int ar = tid >> 2, aseg = tid & 3;
    int acode = codes[ar];
    int br = tid >> 4, bc = (tid & 15) * 4;
    int tx = tid & 15, ty = tid >> 4;

    float c[4][4];
#pragma unroll
    for (int i = 0; i < 4; i++)
#pragma unroll
        for (int j = 0; j < 4; j++) c[i][j] = 0.f;

    for (int k0 = 0; k0 < II; k0 += 16) {
        float4 av = *(const float4*)(g_act + (size_t)acode * II + k0 + aseg * 4);
        As[aseg * 4 + 0][ar] = av.x;
        As[aseg * 4 + 1][ar] = av.y;
        As[aseg * 4 + 2][ar] = av.z;
        As[aseg * 4 + 3][ar] = av.w;
        *(float4*)&Bs[br][bc] = *(const float4*)(wb + (size_t)(k0 + br) * HH + n0 + bc);
        __syncthreads();
#pragma unroll
        for (int k = 0; k < 16; k++) {
            float4 a4 = *(float4*)&As[k][ty * 4];
            float4 b4 = *(float4*)&Bs[k][tx * 4];
            float a[4] = {a4.x, a4.y, a4.z, a4.w};
            float b[4] = {b4.x, b4.y, b4.z, b4.w};
#pragma unroll
            for (int mi = 0; mi < 4; mi++)
#pragma unroll
                for (int ni = 0; ni < 4; ni++) c[mi][ni] += a[mi] * b[ni];
        }
        __syncthreads();
    }

#pragma unroll
    for (int mi = 0; mi < 4; mi++) {
        int r = row0 + ty * 4 + mi;
        if (r >= cnt) continue;
        int code = codes[ty * 4 + mi];
        float* outp = g_downbuf + (size_t)code * HH + n0 + tx * 4;
#pragma unroll
        for (int ni = 0; ni < 4; ni++) outp[ni] = c[mi][ni];
    }
}

// ---------------- shared expert: fused gate+up GEMM ----------------
// grid: (ISH/64, TT/64); block 256
__global__ void __launch_bounds__(256) sh_gateup_kernel(const float* __restrict__ x,
                                                        const float* __restrict__ swg,
                                                        const float* __restrict__ swu) {
    int row0 = blockIdx.y * 64;
    int n0 = blockIdx.x * 64;
    __shared__ float As[16][68];
    __shared__ float Bg[16][64];
    __shared__ float Bu[16][64];
    int tid = threadIdx.x;
    int ar = tid >> 2, aseg = tid & 3;
    int br = tid >> 4, bc = (tid & 15) * 4;
    int tx = tid & 15, ty = tid >> 4;

    float cg[4][4], cu[4][4];
#pragma unroll
    for (int i = 0; i < 4; i++)
#pragma unroll
        for (int j = 0; j < 4; j++) { cg[i][j] = 0.f; cu[i][j] = 0.f; }

    for (int k0 = 0; k0 < HH; k0 += 16) {
        float4 av = *(const float4*)(x + (size_t)(row0 + ar) * HH + k0 + aseg * 4);
        As[aseg * 4 + 0][ar] = av.x;
        As[aseg * 4 + 1][ar] = av.y;
        As[aseg * 4 + 2][ar] = av.z;
        As[aseg * 4 + 3][ar] = av.w;
        *(float4*)&Bg[br][bc] = *(const float4*)(swg + (size_t)(k0 + br) * ISH + n0 + bc);
        *(float4*)&Bu[br][bc] = *(const float4*)(swu + (size_t)(k0 + br) * ISH + n0 + bc);
        __syncthreads();
#pragma unroll
        for (int k = 0; k < 16; k++) {
            float4 a4 = *(float4*)&As[k][ty * 4];
            float4 g4 = *(float4*)&Bg[k][tx * 4];
            float4 u4 = *(float4*)&Bu[k][tx * 4];
            float a[4] = {a4.x, a4.y, a4.z, a4.w};
            float bg[4] = {g4.x, g4.y, g4.z, g4.w};
            float bu[4] = {u4.x, u4.y, u4.z, u4.w};
#pragma unroll
            for (int mi = 0; mi < 4; mi++)
#pragma unroll
                for (int ni = 0; ni < 4; ni++) {
                    cg[mi][ni] += a[mi] * bg[ni];
                    cu[mi][ni] += a[mi] * bu[ni];
                }
        }
        __syncthreads();
    }
#pragma unroll
    for (int mi = 0; mi < 4; mi++) {
        int t = row0 + ty * 4 + mi;
        float* outp = g_shact + (size_t)t * ISH + n0 + tx * 4;
#pragma unroll
        for (int ni = 0; ni < 4; ni++) {
            float gv = cg[mi][ni];
            outp[ni] = (gv / (1.f + __expf(-gv))) * cu[mi][ni];
        }
    }
}

// ---------------- shared expert: down GEMM ----------------
// grid: (HH/64, TT/64); block 256
__global__ void __launch_bounds__(256) sh_down_kernel(const float* __restrict__ swd) {
    int row0 = blockIdx.y * 64;
    int n0 = blockIdx.x * 64;
    __shared__ float As[16][68];
    __shared__ float Bs[16][64];
    int tid = threadIdx.x;
    int ar = tid >> 2, aseg = tid & 3;
    int br = tid >> 4, bc = (tid & 15) * 4;
    int tx = tid & 15, ty = tid >> 4;

    float c[4][4];
#pragma unroll
    for (int i = 0; i < 4; i++)
#pragma unroll
        for (int j = 0; j < 4; j++) c[i][j] = 0.f;

    for (int k0 = 0; k0 < ISH; k0 += 16) {
        float4 av = *(const float4*)(g_shact + (size_t)(row0 + ar) * ISH + k0 + aseg * 4);
        As[aseg * 4 + 0][ar] = av.x;
        As[aseg * 4 + 1][ar] = av.y;
        As[aseg * 4 + 2][ar] = av.z;
        As[aseg * 4 + 3][ar] = av.w;
        *(float4*)&Bs[br][bc] = *(const float4*)(swd + (size_t)(k0 + br) * HH + n0 + bc);
        __syncthreads();
#pragma unroll
        for (int k = 0; k < 16; k++) {
            float4 a4 = *(float4*)&As[k][ty * 4];
            float4 b4 = *(float4*)&Bs[k][tx * 4];
            float a[4] = {a4.x, a4.y, a4.z, a4.w};
            float b[4] = {b4.x, b4.y, b4.z, b4.w};
#pragma unroll
            for (int mi = 0; mi < 4; mi++)
#pragma unroll
                for (int ni = 0; ni < 4; ni++) c[mi][ni] += a[mi] * b[ni];
        }
        __syncthreads();
    }
#pragma unroll
    for (int mi = 0; mi < 4; mi++) {
        int t = row0 + ty * 4 + mi;
        float* outp = g_shdown + (size_t)t * HH + n0 + tx * 4;
#pragma unroll
        for (int ni = 0; ni < 4; ni++) outp[ni] = c[mi][ni];
    }
}

// ---------------- final combine: 4 routed partials + shared expert ----------------
__global__ void combine_kernel(float* __restrict__ out) {
    int i = blockIdx.x * blockDim.x + threadIdx.x;
    if (i >= TT * HH) return;
    int t = i / HH, h = i - t * HH;
    float v = g_shdown[i];
    size_t base = (size_t)t * KTOP * HH + h;
#pragma unroll
    for (int k = 0; k < KTOP; k++) v += g_downbuf[base + (size_t)k * HH];
    out[i] = v;
}

extern "C" void kernel_launch(void* const* d_in, const int* in_sizes, int n_in,
                              void* d_out, int out_size) {
    const float* x       = (const float*)d_in[0];
    const float* gate_w  = (const float*)d_in[1];
    const float* w_gate  = (const float*)d_in[2];
    const float* w_up    = (const float*)d_in[3];
    const float* w_down  = (const float*)d_in[4];
    const float* sw_gate = (const float*)d_in[5];
    const float* sw_up   = (const float*)d_in[6];
    const float* sw_down = (const float*)d_in[7];
    float* out = (float*)d_out;

    zero_counts_kernel<<<1, 32>>>();
    router_kernel<<<TT / 4, 128>>>(x, gate_w);
    gateup_kernel<<<dim3(II / 64, TT / 64, EE), 256>>>(x, w_gate, w_up);
    down_kernel<<<dim3(HH / 64, TT / 64, EE), 256>>>(w_down);
    sh_gateup_kernel<<<dim3(ISH / 64, TT / 64), 256>>>(x, sw_gate, sw_up);
    sh_down_kernel<<<dim3(HH / 64, TT / 64), 256>>>(sw_down);
    combine_kernel<<<(TT * HH + 255) / 256, 256>>>(out);
}

// round 5
// speedup vs baseline: 1.9709x; 1.9709x over previous
#include <cuda_runtime.h>
#include <cuda_bf16.h>
#include <math.h>
#include <stdint.h>

#define TT 1024
#define HH 2048
#define EE 16
#define KTOP 4
#define II 1408
#define ISH 2816

// ---------------- scratch ----------------
__device__ float g_gu[(size_t)TT * KTOP * 2 * II];
__device__ float g_act[(size_t)TT * KTOP * II];
__device__ float g_downbuf[(size_t)TT * KTOP * HH];
__device__ float g_sgu[(size_t)TT * 2 * ISH];
__device__ float g_shact[(size_t)TT * ISH];
__device__ float g_shdown[(size_t)TT * HH];
__device__ int   g_counts[EE];
__device__ int   g_list[EE * TT];
__device__ float g_tw[TT * KTOP];

// Device-side resolution of scratch buffers (NEVER pass __device__ globals
// as kernel arguments from host code — host sees the shadow symbol address).
__device__ __forceinline__ float* buf_ptr(int sel) {
    switch (sel) {
        case 1: return g_act;
        case 2: return g_downbuf;
        case 3: return g_sgu;
        case 4: return g_shact;
        case 5: return g_shdown;
        default: return g_gu;
    }
}

// ---------------- helpers ----------------
__device__ __forceinline__ uint32_t smem_u32(const void* p) {
    uint32_t a;
    asm("{ .reg .u64 t; cvta.to.shared.u64 t, %1; cvt.u32.u64 %0, t; }" : "=r"(a) : "l"(p));
    return a;
}
__device__ __forceinline__ void ldsm4(uint32_t* r, uint32_t addr) {
    asm volatile("ldmatrix.sync.aligned.m8n8.x4.shared.b16 {%0,%1,%2,%3}, [%4];"
                 : "=r"(r[0]), "=r"(r[1]), "=r"(r[2]), "=r"(r[3]) : "r"(addr));
}
__device__ __forceinline__ void ldsm2(uint32_t* r, uint32_t addr) {
    asm volatile("ldmatrix.sync.aligned.m8n8.x2.shared.b16 {%0,%1}, [%2];"
                 : "=r"(r[0]), "=r"(r[1]) : "r"(addr));
}
__device__ __forceinline__ void mma16816(float* c, const uint32_t* a, const uint32_t* b) {
    asm volatile(
        "mma.sync.aligned.m16n8k16.row.col.f32.bf16.bf16.f32 "
        "{%0,%1,%2,%3}, {%4,%5,%6,%7}, {%8,%9}, {%0,%1,%2,%3};"
        : "+f"(c[0]), "+f"(c[1]), "+f"(c[2]), "+f"(c[3])
        : "r"(a[0]), "r"(a[1]), "r"(a[2]), "r"(a[3]), "r"(b[0]), "r"(b[1]));
}
__device__ __forceinline__ void cvt_hilo(float x, float y, uint32_t& hi, uint32_t& lo) {
    __nv_bfloat162 h = __floats2bfloat162_rn(x, y);
    float2 hf = __bfloat1622float2(h);
    __nv_bfloat162 l = __floats2bfloat162_rn(x - hf.x, y - hf.y);
    hi = *(uint32_t*)&h;
    lo = *(uint32_t*)&l;
}

// ---------------- tile config ----------------
#define PAD 40                       // bf16 elems per smem row (80B) -> conflict-free ldmatrix
#define TILE_B (128 * PAD * 2)       // 10240 bytes per sub-buffer (AH/AL/BH/BL)
#define STAGE_B (4 * TILE_B)         // 40960 bytes

// MODE: 0 = dense, 1 = gather token (A row = code>>2), 2 = gather code
template <int MODE>
__global__ void __launch_bounds__(256) gemm_mma(
    const float* __restrict__ Aext, int a_sel, int lda,
    const float* __restrict__ B1, const float* __restrict__ B2,
    int ldb, int nsplit,
    long bstride1, long bstride2,
    int c_sel, int ldc,
    int Ktot, int Mtot)
{
    __shared__ int codes[128];
    __shared__ __align__(16) char stage[STAGE_B];

    const float* A = (a_sel < 0) ? Aext : buf_ptr(a_sel);
    float* C = buf_ptr(c_sel);

    int e = blockIdx.z;
    int row0 = blockIdx.y * 128;
    int cnt;
    const int* list = nullptr;
    if (MODE != 0) {
        cnt = g_counts[e];
        if (row0 >= cnt) return;
        list = g_list + e * TT;
    } else {
        cnt = Mtot;
        if (row0 >= cnt) return;
    }

    int tid = threadIdx.x;
    int wid = tid >> 5;
    int lane = tid & 31;

    if (tid < 128) {
        int r = row0 + tid;
        if (r >= cnt) r = cnt - 1;
        codes[tid] = (MODE != 0) ? list[r] : r;
    }
    __syncthreads();

    int n0 = blockIdx.x * 128;
    const float* B;
    if (n0 < nsplit) { B = B1 + (size_t)e * bstride1 + n0; }
    else             { B = B2 + (size_t)e * bstride2 + (n0 - nsplit); }

    // loader roles
    int arow_idx = tid >> 1, ahalf = tid & 1;          // A: row 0..127, 16-float half
    int a_src_row;
    {
        int code = codes[arow_idx];
        a_src_row = (MODE == 1) ? (code >> 2) : code;
    }
    const float* a_base = A + (size_t)a_src_row * lda + ahalf * 16;

    int bn = tid & 127, bkh = tid >> 7;                // B: col n, 16-k half
    const float* b_base = B + bn;

    // compute roles
    int wm = (wid >> 2) * 64;
    int wn = (wid & 3) * 32;
    uint32_t sb = smem_u32(stage);
    int lrow = lane & 15, lkh = lane >> 4;
    int brow = lane & 7, bhalf = (lane >> 3) & 1;

    float c[4][4][4];
#pragma unroll
    for (int i = 0; i < 4; i++)
#pragma unroll
        for (int j = 0; j < 4; j++)
#pragma unroll
            for (int q = 0; q < 4; q++) c[i][j][q] = 0.f;

    int nt = Ktot >> 5;  // BK = 32

    float4 a_reg[4];
    float b_reg[16];

    // prefetch tile 0
#pragma unroll
    for (int j = 0; j < 4; j++) a_reg[j] = *(const float4*)(a_base + j * 4);
#pragma unroll
    for (int kk = 0; kk < 16; kk++) b_reg[kk] = b_base[(size_t)(bkh * 16 + kk) * ldb];

    __nv_bfloat16* pAh = (__nv_bfloat16*)stage;
    __nv_bfloat16* pBh = (__nv_bfloat16*)(stage + 2 * TILE_B);

    for (int t = 0; t < nt; t++) {
        // ---- store current regs -> smem (fp32 -> bf16 hi/lo) ----
#pragma unroll
        for (int j = 0; j < 4; j++) {
            uint32_t h0, l0, h1, l1;
            cvt_hilo(a_reg[j].x, a_reg[j].y, h0, l0);
            cvt_hilo(a_reg[j].z, a_reg[j].w, h1, l1);
            int off = arow_idx * PAD + ahalf * 16 + j * 4;
            *(uint2*)(pAh + off) = make_uint2(h0, h1);
            *(uint2*)((char*)(pAh + off) + TILE_B) = make_uint2(l0, l1);
        }
#pragma unroll
        for (int q = 0; q < 4; q++) {
            uint32_t h0, l0, h1, l1;
            cvt_hilo(b_reg[q * 4 + 0], b_reg[q * 4 + 1], h0, l0);
            cvt_hilo(b_reg[q * 4 + 2], b_reg[q * 4 + 3], h1, l1);
            int off = bn * PAD + bkh * 16 + q * 4;
            *(uint2*)(pBh + off) = make_uint2(h0, h1);
            *(uint2*)((char*)(pBh + off) + TILE_B) = make_uint2(l0, l1);
        }
        __syncthreads();

        // ---- prefetch next tile into regs (overlaps with mma below) ----
        if (t + 1 < nt) {
            int k0 = (t + 1) << 5;
#pragma unroll
            for (int j = 0; j < 4; j++) a_reg[j] = *(const float4*)(a_base + k0 + j * 4);
#pragma unroll
            for (int kk = 0; kk < 16; kk++) b_reg[kk] = b_base[(size_t)(k0 + bkh * 16 + kk) * ldb];
        }

        // ---- compute ----
#pragma unroll
        for (int kt = 0; kt < 2; kt++) {
            uint32_t ah[4][4], al[4][4], bh[4][2], bl[4][2];
#pragma unroll
            for (int mi = 0; mi < 4; mi++) {
                uint32_t adr = sb + 2u * (uint32_t)((wm + mi * 16 + lrow) * PAD + kt * 16 + lkh * 8);
                ldsm4(ah[mi], adr);
                ldsm4(al[mi], adr + TILE_B);
            }
#pragma unroll
            for (int ni = 0; ni < 4; ni++) {
                uint32_t adr = sb + 2u * TILE_B +
                               2u * (uint32_t)((wn + ni * 8 + brow) * PAD + kt * 16 + bhalf * 8);
                ldsm2(bh[ni], adr);
                ldsm2(bl[ni], adr + TILE_B);
            }
#pragma unroll
            for (int mi = 0; mi < 4; mi++)
#pragma unroll
                for (int ni = 0; ni < 4; ni++) {
                    mma16816(c[mi][ni], ah[mi], bh[ni]);
                    mma16816(c[mi][ni], ah[mi], bl[ni]);
                    mma16816(c[mi][ni], al[mi], bh[ni]);
                }
        }
        __syncthreads();
    }

    // ---- epilogue ----
    int g = lane >> 2, tig = lane & 3;
#pragma unroll
    for (int mi = 0; mi < 4; mi++) {
        int m1 = wm + mi * 16 + g;
        int m2 = m1 + 8;
        bool v1 = (row0 + m1) < cnt;
        bool v2 = (row0 + m2) < cnt;
        int cr1 = codes[m1], cr2 = codes[m2];
        float* p1 = C + (size_t)cr1 * ldc + n0 + wn + tig * 2;
        float* p2 = C + (size_t)cr2 * ldc + n0 + wn + tig * 2;
#pragma unroll
        for (int ni = 0; ni < 4; ni++) {
            if (v1) *(float2*)(p1 + ni * 8) = make_float2(c[mi][ni][0], c[mi][ni][1]);
            if (v2) *(float2*)(p2 + ni * 8) = make_float2(c[mi][ni][2], c[mi][ni][3]);
        }
    }
}

// ---------------- router ----------------
__global__ void zero_counts_kernel() {
    if (threadIdx.x < EE) g_counts[threadIdx.x] = 0;
}

__global__ void router_kernel(const float* __restrict__ x, const float* __restrict__ gw) {
    int t = blockIdx.x * 4 + (threadIdx.x >> 5);
    int lane = threadIdx.x & 31;
    if (t >= TT) return;
    float acc[EE];
#pragma unroll
    for (int e = 0; e < EE; e++) acc[e] = 0.f;
    const float* xr = x + (size_t)t * HH;
    for (int h = lane; h < HH; h += 32) {
        float xv = xr[h];
#pragma unroll
        for (int e = 0; e < EE; e++) acc[e] += xv * gw[e * HH + h];
    }
#pragma unroll
    for (int e = 0; e < EE; e++) {
#pragma unroll
        for (int o = 16; o > 0; o >>= 1) acc[e] += __shfl_xor_sync(0xffffffffu, acc[e], o);
    }
    if (lane == 0) {
        float m = acc[0];
#pragma unroll
        for (int e = 1; e < EE; e++) m = fmaxf(m, acc[e]);
        float sc[EE];
        float sum = 0.f;
#pragma unroll
        for (int e = 0; e < EE; e++) { sc[e] = expf(acc[e] - m); sum += sc[e]; }
        float inv = 1.f / sum;
#pragma unroll
        for (int e = 0; e < EE; e++) sc[e] *= inv;
        int idx[KTOP]; float w[KTOP]; float wsum = 0.f;
#pragma unroll
        for (int k = 0; k < KTOP; k++) {
            int bi = 0; float bv = -1.f;
#pragma unroll
            for (int e = 0; e < EE; e++) if (sc[e] > bv) { bv = sc[e]; bi = e; }
            idx[k] = bi; w[k] = bv; sc[bi] = -2.f; wsum += bv;
        }
        float winv = 1.f / wsum;
        for (int k = 0; k < KTOP; k++) {
            int code = t * KTOP + k;
            g_tw[code] = w[k] * winv;
            int pos = atomicAdd(&g_counts[idx[k]], 1);
            g_list[idx[k] * TT + pos] = code;
        }
    }
}

// ---------------- elementwise ----------------
__global__ void act_routed_kernel() {
    int v = blockIdx.x * blockDim.x + threadIdx.x;
    const int per = II / 4;
    if (v >= TT * KTOP * per) return;
    int code = v / per, c4 = v - code * per;
    const float* row = g_gu + (size_t)code * (2 * II);
    float4 g4 = *(const float4*)(row + c4 * 4);
    float4 u4 = *(const float4*)(row + II + c4 * 4);
    float w = g_tw[code];
    float4 o;
    o.x = (g4.x / (1.f + __expf(-g4.x))) * u4.x * w;
    o.y = (g4.y / (1.f + __expf(-g4.y))) * u4.y * w;
    o.z = (g4.z / (1.f + __expf(-g4.z))) * u4.z * w;
    o.w = (g4.w / (1.f + __expf(-g4.w))) * u4.w * w;
    *(float4*)(g_act + (size_t)code * II + c4 * 4) = o;
}

__global__ void act_shared_kernel() {
    int v = blockIdx.x * blockDim.x + threadIdx.x;
    const int per = ISH / 4;
    if (v >= TT * per) return;
    int t = v / per, c4 = v - t * per;
    const float* row = g_sgu + (size_t)t * (2 * ISH);
    float4 g4 = *(const float4*)(row + c4 * 4);
    float4 u4 = *(const float4*)(row + ISH + c4 * 4);
    float4 o;
    o.x = (g4.x / (1.f + __expf(-g4.x))) * u4.x;
    o.y = (g4.y / (1.f + __expf(-g4.y))) * u4.y;
    o.z = (g4.z / (1.f + __expf(-g4.z))) * u4.z;
    o.w = (g4.w / (1.f + __expf(-g4.w))) * u4.w;
    *(float4*)(g_shact + (size_t)t * ISH + c4 * 4) = o;
}

__global__ void combine_kernel(float* __restrict__ out) {
    int v = blockIdx.x * blockDim.x + threadIdx.x;
    const int per = HH / 4;
    if (v >= TT * per) return;
    int t = v / per, h4 = v - t * per;
    float4 acc = *(const float4*)(g_shdown + (size_t)t * HH + h4 * 4);
#pragma unroll
    for (int k = 0; k < KTOP; k++) {
        float4 d = *(const float4*)(g_downbuf + (size_t)(t * KTOP + k) * HH + h4 * 4);
        acc.x += d.x; acc.y += d.y; acc.z += d.z; acc.w += d.w;
    }
    *(float4*)(out + (size_t)t * HH + h4 * 4) = acc;
}

// ---------------- launch ----------------
extern "C" void kernel_launch(void* const* d_in, const int* in_sizes, int n_in,
                              void* d_out, int out_size) {
    const float* x       = (const float*)d_in[0];
    const float* gate_w  = (const float*)d_in[1];
    const float* w_gate  = (const float*)d_in[2];
    const float* w_up    = (const float*)d_in[3];
    const float* w_down  = (const float*)d_in[4];
    const float* sw_gate = (const float*)d_in[5];
    const float* sw_up   = (const float*)d_in[6];
    const float* sw_down = (const float*)d_in[7];
    float* out = (float*)d_out;

    zero_counts_kernel<<<1, 32>>>();
    router_kernel<<<TT / 4, 128>>>(x, gate_w);

    // routed gate+up: C = g_gu (sel 0), A = x
    gemm_mma<1><<<dim3(2 * II / 128, TT / 128, EE), 256>>>(
        x, -1, HH, w_gate, w_up, II, II,
        (long)HH * II, (long)HH * II, 0, 2 * II, HH, 0);

    act_routed_kernel<<<(TT * KTOP * (II / 4) + 255) / 256, 256>>>();

    // routed down: C = g_downbuf (sel 2), A = g_act (sel 1)
    gemm_mma<2><<<dim3(HH / 128, TT / 128, EE), 256>>>(
        nullptr, 1, II, w_down, w_down, HH, HH,
        (long)II * HH, 0, 2, HH, II, 0);

    // shared gate+up: C = g_sgu (sel 3), A = x
    gemm_mma<0><<<dim3(2 * ISH / 128, TT / 128, 1), 256>>>(
        x, -1, HH, sw_gate, sw_up, ISH, ISH,
        0, 0, 3, 2 * ISH, HH, TT);

    act_shared_kernel<<<(TT * (ISH / 4) + 255) / 256, 256>>>();

    // shared down: C = g_shdown (sel 5), A = g_shact (sel 4)
    gemm_mma<0><<<dim3(HH / 128, TT / 128, 1), 256>>>(
        nullptr, 4, ISH, sw_down, sw_down, HH, HH,
        0, 0, 5, HH, ISH, TT);

    combine_kernel<<<(TT * (HH / 4) + 255) / 256, 256>>>(out);
}

// round 7
// speedup vs baseline: 2.2390x; 1.1360x over previous
#include <cuda_runtime.h>
#include <cuda_bf16.h>
#include <math.h>
#include <stdint.h>

#define TT 1024
#define HH 2048
#define EE 16
#define KTOP 4
#define II 1408
#define ISH 2816

// ---------------- scratch ----------------
__device__ float g_gu[(size_t)TT * KTOP * 2 * II];
__device__ float g_act[(size_t)TT * KTOP * II];
__device__ float g_downbuf[(size_t)TT * KTOP * HH];
__device__ float g_sgu[(size_t)TT * 2 * ISH];
__device__ float g_shact[(size_t)TT * ISH];
__device__ float g_shdown[(size_t)TT * HH];
__device__ int   g_counts[EE];
__device__ int   g_list[EE * TT];
__device__ float g_tw[TT * KTOP];

__device__ __forceinline__ float* buf_ptr(int sel) {
    switch (sel) {
        case 1: return g_act;
        case 2: return g_downbuf;
        case 3: return g_sgu;
        case 4: return g_shact;
        case 5: return g_shdown;
        default: return g_gu;
    }
}

// ---------------- helpers ----------------
__device__ __forceinline__ uint32_t smem_u32(const void* p) {
    uint32_t a;
    asm("{ .reg .u64 t; cvta.to.shared.u64 t, %1; cvt.u32.u64 %0, t; }" : "=r"(a) : "l"(p));
    return a;
}
__device__ __forceinline__ void ldsm4(uint32_t* r, uint32_t addr) {
    asm volatile("ldmatrix.sync.aligned.m8n8.x4.shared.b16 {%0,%1,%2,%3}, [%4];"
                 : "=r"(r[0]), "=r"(r[1]), "=r"(r[2]), "=r"(r[3]) : "r"(addr));
}
__device__ __forceinline__ void ldsm2(uint32_t* r, uint32_t addr) {
    asm volatile("ldmatrix.sync.aligned.m8n8.x2.shared.b16 {%0,%1}, [%2];"
                 : "=r"(r[0]), "=r"(r[1]) : "r"(addr));
}
__device__ __forceinline__ void mma16816(float* c, const uint32_t* a, const uint32_t* b) {
    asm volatile(
        "mma.sync.aligned.m16n8k16.row.col.f32.bf16.bf16.f32 "
        "{%0,%1,%2,%3}, {%4,%5,%6,%7}, {%8,%9}, {%0,%1,%2,%3};"
        : "+f"(c[0]), "+f"(c[1]), "+f"(c[2]), "+f"(c[3])
        : "r"(a[0]), "r"(a[1]), "r"(a[2]), "r"(a[3]), "r"(b[0]), "r"(b[1]));
}
__device__ __forceinline__ void cvt_hilo(float x, float y, uint32_t& hi, uint32_t& lo) {
    __nv_bfloat162 h = __floats2bfloat162_rn(x, y);
    float2 hf = __bfloat1622float2(h);
    __nv_bfloat162 l = __floats2bfloat162_rn(x - hf.x, y - hf.y);
    hi = *(uint32_t*)&h;
    lo = *(uint32_t*)&l;
}

// ---------------- tile config ----------------
// Row layout: [16 bf16 hi | 16 bf16 lo | 8 pad] = 40 elems = 80B stride.
#define RSTRIDE 40
#define TILE_B (128 * RSTRIDE * 2)   // 10240 bytes per operand tile (hi+lo packed)
#define STAGE_B (2 * TILE_B)         // A + B = 20480 bytes per stage

// MODE: 0 = dense, 1 = gather token (A row = code>>2), 2 = gather code
template <int MODE>
__global__ void __launch_bounds__(256, 2) gemm_mma(
    const float* __restrict__ Aext, int a_sel, int lda,
    const float* __restrict__ B1, const float* __restrict__ B2,
    int ldb, int nsplit,
    long bstride1, long bstride2,
    int c_sel, int ldc,
    int Ktot, int Mtot)
{
    __shared__ int codes[128];
    __shared__ __align__(16) char stage[2 * STAGE_B];   // 40 KB static

    const float* A = (a_sel < 0) ? Aext : buf_ptr(a_sel);
    float* C = buf_ptr(c_sel);

    int e = blockIdx.z;
    int row0 = blockIdx.y * 128;
    int cnt;
    const int* list = nullptr;
    if (MODE != 0) {
        cnt = g_counts[e];
        if (row0 >= cnt) return;
        list = g_list + e * TT;
    } else {
        cnt = Mtot;
        if (row0 >= cnt) return;
    }

    int tid = threadIdx.x;
    int wid = tid >> 5;
    int lane = tid & 31;

    if (tid < 128) {
        int r = row0 + tid;
        if (r >= cnt) r = cnt - 1;
        codes[tid] = (MODE != 0) ? list[r] : r;
    }
    __syncthreads();

    int n0 = blockIdx.x * 128;
    const float* B;
    if (n0 < nsplit) { B = B1 + (size_t)e * bstride1 + n0; }
    else             { B = B2 + (size_t)e * bstride2 + (n0 - nsplit); }

    // loader roles: BK = 16
    int arow_idx = tid >> 1, ahalf = tid & 1;
    int a_src_row;
    {
        int code = codes[arow_idx];
        a_src_row = (MODE == 1) ? (code >> 2) : code;
    }
    const float* a_base = A + (size_t)a_src_row * lda + ahalf * 8;
    int bn = tid & 127, bk0 = (tid >> 7) * 8;
    const float* b_base = B + bn + (size_t)bk0 * ldb;

    // compute roles
    int wm = (wid >> 2) * 64;
    int wn = (wid & 3) * 32;
    uint32_t sb = smem_u32(stage);
    int lrow = lane & 15, lkh = lane >> 4;
    int brow = lane & 7, bhalf = (lane >> 3) & 1;

    float c[4][4][4];
#pragma unroll
    for (int i = 0; i < 4; i++)
#pragma unroll
        for (int j = 0; j < 4; j++)
#pragma unroll
            for (int q = 0; q < 4; q++) c[i][j][q] = 0.f;

    int nt = Ktot >> 4;  // BK = 16

    float4 a_reg[2];
    float b_reg[8];

    __nv_bfloat16* sA = (__nv_bfloat16*)stage;
    __nv_bfloat16* sB = (__nv_bfloat16*)(stage + TILE_B);

    auto load_tile = [&](int t) {
        const float* ap = a_base + (t << 4);
        a_reg[0] = *(const float4*)(ap);
        a_reg[1] = *(const float4*)(ap + 4);
        const float* bp = b_base + (size_t)(t << 4) * ldb;
#pragma unroll
        for (int kk = 0; kk < 8; kk++) b_reg[kk] = bp[(size_t)kk * ldb];
    };
    auto store_tile = [&](int s) {
        __nv_bfloat16* pA = sA + (size_t)s * (STAGE_B / 2);   // element arithmetic: full stage
        __nv_bfloat16* pB = sB + (size_t)s * (STAGE_B / 2);
        {
            uint32_t h0, l0, h1, l1, h2, l2, h3, l3;
            cvt_hilo(a_reg[0].x, a_reg[0].y, h0, l0);
            cvt_hilo(a_reg[0].z, a_reg[0].w, h1, l1);
            cvt_hilo(a_reg[1].x, a_reg[1].y, h2, l2);
            cvt_hilo(a_reg[1].z, a_reg[1].w, h3, l3);
            int off = arow_idx * RSTRIDE + ahalf * 8;
            *(uint4*)(pA + off) = make_uint4(h0, h1, h2, h3);
            *(uint4*)(pA + off + 16) = make_uint4(l0, l1, l2, l3);
        }
        {
            uint32_t h0, l0, h1, l1, h2, l2, h3, l3;
            cvt_hilo(b_reg[0], b_reg[1], h0, l0);
            cvt_hilo(b_reg[2], b_reg[3], h1, l1);
            cvt_hilo(b_reg[4], b_reg[5], h2, l2);
            cvt_hilo(b_reg[6], b_reg[7], h3, l3);
            int off = bn * RSTRIDE + bk0;
            *(uint4*)(pB + off) = make_uint4(h0, h1, h2, h3);
            *(uint4*)(pB + off + 16) = make_uint4(l0, l1, l2, l3);
        }
    };

    // ---- prologue ----
    load_tile(0);
    store_tile(0);
    if (nt > 1) load_tile(1);
    __syncthreads();

    for (int t = 0; t < nt; t++) {
        int s = t & 1;
        uint32_t stA = sb + (uint32_t)s * STAGE_B;      // BYTE offset: full stage (bug fix)
        uint32_t stB = stA + (uint32_t)TILE_B;

        uint32_t bh[4][2], bl[4][2];
#pragma unroll
        for (int ni = 0; ni < 4; ni++) {
            uint32_t adr = stB + 2u * (uint32_t)((wn + ni * 8 + brow) * RSTRIDE + bhalf * 8);
            ldsm2(bh[ni], adr);
            ldsm2(bl[ni], adr + 32);
        }
#pragma unroll
        for (int mi = 0; mi < 4; mi++) {
            uint32_t ah[4], al[4];
            uint32_t adr = stA + 2u * (uint32_t)((wm + mi * 16 + lrow) * RSTRIDE + lkh * 8);
            ldsm4(ah, adr);
            ldsm4(al, adr + 32);
#pragma unroll
            for (int ni = 0; ni < 4; ni++) {
                mma16816(c[mi][ni], ah, bh[ni]);
                mma16816(c[mi][ni], ah, bl[ni]);
                mma16816(c[mi][ni], al, bh[ni]);
            }
        }

        if (t + 1 < nt) store_tile(1 - s);
        if (t + 2 < nt) load_tile(t + 2);
        __syncthreads();
    }

    // ---- epilogue ----
    int g = lane >> 2, tig = lane & 3;
#pragma unroll
    for (int mi = 0; mi < 4; mi++) {
        int m1 = wm + mi * 16 + g;
        int m2 = m1 + 8;
        bool v1 = (row0 + m1) < cnt;
        bool v2 = (row0 + m2) < cnt;
        int cr1 = codes[m1], cr2 = codes[m2];
        float* p1 = C + (size_t)cr1 * ldc + n0 + wn + tig * 2;
        float* p2 = C + (size_t)cr2 * ldc + n0 + wn + tig * 2;
#pragma unroll
        for (int ni = 0; ni < 4; ni++) {
            if (v1) *(float2*)(p1 + ni * 8) = make_float2(c[mi][ni][0], c[mi][ni][1]);
            if (v2) *(float2*)(p2 + ni * 8) = make_float2(c[mi][ni][2], c[mi][ni][3]);
        }
    }
}

// ---------------- router ----------------
__global__ void zero_counts_kernel() {
    if (threadIdx.x < EE) g_counts[threadIdx.x] = 0;
}

__global__ void router_kernel(const float* __restrict__ x, const float* __restrict__ gw) {
    int t = blockIdx.x * 4 + (threadIdx.x >> 5);
    int lane = threadIdx.x & 31;
    if (t >= TT) return;
    float acc[EE];
#pragma unroll
    for (int e = 0; e < EE; e++) acc[e] = 0.f;
    const float* xr = x + (size_t)t * HH;
    for (int h = lane; h < HH; h += 32) {
        float xv = xr[h];
#pragma unroll
        for (int e = 0; e < EE; e++) acc[e] += xv * gw[e * HH + h];
    }
#pragma unroll
    for (int e = 0; e < EE; e++) {
#pragma unroll
        for (int o = 16; o > 0; o >>= 1) acc[e] += __shfl_xor_sync(0xffffffffu, acc[e], o);
    }
    if (lane == 0) {
        float m = acc[0];
#pragma unroll
        for (int e = 1; e < EE; e++) m = fmaxf(m, acc[e]);
        float sc[EE];
        float sum = 0.f;
#pragma unroll
        for (int e = 0; e < EE; e++) { sc[e] = expf(acc[e] - m); sum += sc[e]; }
        float inv = 1.f / sum;
#pragma unroll
        for (int e = 0; e < EE; e++) sc[e] *= inv;
        int idx[KTOP]; float w[KTOP]; float wsum = 0.f;
#pragma unroll
        for (int k = 0; k < KTOP; k++) {
            int bi = 0; float bv = -1.f;
#pragma unroll
            for (int e = 0; e < EE; e++) if (sc[e] > bv) { bv = sc[e]; bi = e; }
            idx[k] = bi; w[k] = bv; sc[bi] = -2.f; wsum += bv;
        }
        float winv = 1.f / wsum;
        for (int k = 0; k < KTOP; k++) {
            int code = t * KTOP + k;
            g_tw[code] = w[k] * winv;
            int pos = atomicAdd(&g_counts[idx[k]], 1);
            g_list[idx[k] * TT + pos] = code;
        }
    }
}

// ---------------- elementwise ----------------
__global__ void act_routed_kernel() {
    int v = blockIdx.x * blockDim.x + threadIdx.x;
    const int per = II / 4;
    if (v >= TT * KTOP * per) return;
    int code = v / per, c4 = v - code * per;
    const float* row = g_gu + (size_t)code * (2 * II);
    float4 g4 = *(const float4*)(row + c4 * 4);
    float4 u4 = *(const float4*)(row + II + c4 * 4);
    float w = g_tw[code];
    float4 o;
    o.x = (g4.x / (1.f + __expf(-g4.x))) * u4.x * w;
    o.y = (g4.y / (1.f + __expf(-g4.y))) * u4.y * w;
    o.z = (g4.z / (1.f + __expf(-g4.z))) * u4.z * w;
    o.w = (g4.w / (1.f + __expf(-g4.w))) * u4.w * w;
    *(float4*)(g_act + (size_t)code * II + c4 * 4) = o;
}

__global__ void act_shared_kernel() {
    int v = blockIdx.x * blockDim.x + threadIdx.x;
    const int per = ISH / 4;
    if (v >= TT * per) return;
    int t = v / per, c4 = v - t * per;
    const float* row = g_sgu + (size_t)t * (2 * ISH);
    float4 g4 = *(const float4*)(row + c4 * 4);
    float4 u4 = *(const float4*)(row + ISH + c4 * 4);
    float4 o;
    o.x = (g4.x / (1.f + __expf(-g4.x))) * u4.x;
    o.y = (g4.y / (1.f + __expf(-g4.y))) * u4.y;
    o.z = (g4.z / (1.f + __expf(-g4.z))) * u4.z;
    o.w = (g4.w / (1.f + __expf(-g4.w))) * u4.w;
    *(float4*)(g_shact + (size_t)t * ISH + c4 * 4) = o;
}

__global__ void combine_kernel(float* __restrict__ out) {
    int v = blockIdx.x * blockDim.x + threadIdx.x;
    const int per = HH / 4;
    if (v >= TT * per) return;
    int t = v / per, h4 = v - t * per;
    float4 acc = *(const float4*)(g_shdown + (size_t)t * HH + h4 * 4);
#pragma unroll
    for (int k = 0; k < KTOP; k++) {
        float4 d = *(const float4*)(g_downbuf + (size_t)(t * KTOP + k) * HH + h4 * 4);
        acc.x += d.x; acc.y += d.y; acc.z += d.z; acc.w += d.w;
    }
    *(float4*)(out + (size_t)t * HH + h4 * 4) = acc;
}

// ---------------- launch ----------------
extern "C" void kernel_launch(void* const* d_in, const int* in_sizes, int n_in,
                              void* d_out, int out_size) {
    const float* x       = (const float*)d_in[0];
    const float* gate_w  = (const float*)d_in[1];
    const float* w_gate  = (const float*)d_in[2];
    const float* w_up    = (const float*)d_in[3];
    const float* w_down  = (const float*)d_in[4];
    const float* sw_gate = (const float*)d_in[5];
    const float* sw_up   = (const float*)d_in[6];
    const float* sw_down = (const float*)d_in[7];
    float* out = (float*)d_out;

    zero_counts_kernel<<<1, 32>>>();
    router_kernel<<<TT / 4, 128>>>(x, gate_w);

    gemm_mma<1><<<dim3(2 * II / 128, TT / 128, EE), 256>>>(
        x, -1, HH, w_gate, w_up, II, II,
        (long)HH * II, (long)HH * II, 0, 2 * II, HH, 0);

    act_routed_kernel<<<(TT * KTOP * (II / 4) + 255) / 256, 256>>>();

    gemm_mma<2><<<dim3(HH / 128, TT / 128, EE), 256>>>(
        nullptr, 1, II, w_down, w_down, HH, HH,
        (long)II * HH, 0, 2, HH, II, 0);

    gemm_mma<0><<<dim3(2 * ISH / 128, TT / 128, 1), 256>>>(
        x, -1, HH, sw_gate, sw_up, ISH, ISH,
        0, 0, 3, 2 * ISH, HH, TT);

    act_shared_kernel<<<(TT * (ISH / 4) + 255) / 256, 256>>>();

    gemm_mma<0><<<dim3(HH / 128, TT / 128, 1), 256>>>(
        nullptr, 4, ISH, sw_down, sw_down, HH, HH,
        0, 0, 5, HH, ISH, TT);

    combine_kernel<<<(TT * (HH / 4) + 255) / 256, 256>>>(out);
}

// round 8
// speedup vs baseline: 3.0726x; 1.3723x over previous
#include <cuda_runtime.h>
#include <cuda_fp16.h>
#include <math.h>
#include <stdint.h>

#define TT 1024
#define HH 2048
#define EE 16
#define KTOP 4
#define II 1408
#define ISH 2816

// ---------------- scratch ----------------
__device__ float g_gu[(size_t)TT * KTOP * 2 * II];
__device__ float g_act[(size_t)TT * KTOP * II];
__device__ float g_downbuf[(size_t)TT * KTOP * HH];
__device__ float g_sgu[(size_t)TT * 2 * ISH];
__device__ float g_shact[(size_t)TT * ISH];
__device__ float g_shdown[(size_t)TT * HH];
__device__ int   g_counts[EE];
__device__ int   g_list[EE * TT];
__device__ float g_tw[TT * KTOP];

__device__ __forceinline__ float* buf_ptr(int sel) {
    switch (sel) {
        case 1: return g_act;
        case 2: return g_downbuf;
        case 3: return g_sgu;
        case 4: return g_shact;
        case 5: return g_shdown;
        default: return g_gu;
    }
}

// ---------------- helpers ----------------
__device__ __forceinline__ uint32_t smem_u32(const void* p) {
    uint32_t a;
    asm("{ .reg .u64 t; cvta.to.shared.u64 t, %1; cvt.u32.u64 %0, t; }" : "=r"(a) : "l"(p));
    return a;
}
__device__ __forceinline__ void ldsm4(uint32_t* r, uint32_t addr) {
    asm volatile("ldmatrix.sync.aligned.m8n8.x4.shared.b16 {%0,%1,%2,%3}, [%4];"
                 : "=r"(r[0]), "=r"(r[1]), "=r"(r[2]), "=r"(r[3]) : "r"(addr));
}
__device__ __forceinline__ void ldsm2(uint32_t* r, uint32_t addr) {
    asm volatile("ldmatrix.sync.aligned.m8n8.x2.shared.b16 {%0,%1}, [%2];"
                 : "=r"(r[0]), "=r"(r[1]) : "r"(addr));
}
__device__ __forceinline__ void mma16816(float* c, const uint32_t* a, const uint32_t* b) {
    asm volatile(
        "mma.sync.aligned.m16n8k16.row.col.f32.f16.f16.f32 "
        "{%0,%1,%2,%3}, {%4,%5,%6,%7}, {%8,%9}, {%0,%1,%2,%3};"
        : "+f"(c[0]), "+f"(c[1]), "+f"(c[2]), "+f"(c[3])
        : "r"(a[0]), "r"(a[1]), "r"(a[2]), "r"(a[3]), "r"(b[0]), "r"(b[1]));
}
__device__ __forceinline__ uint32_t packh2(float x, float y) {
    __half2 h = __floats2half2_rn(x, y);
    return *(uint32_t*)&h;
}

// ---------------- tile config ----------------
// BK = 32. Row layout: 32 fp16 + 8 pad = 40 elems = 80B stride (conflict-free ldmatrix).
#define RSTRIDE 40
#define TILE_B (128 * RSTRIDE * 2)   // 10240 bytes per operand tile
#define STAGE_B (2 * TILE_B)         // A + B = 20480 bytes per stage

// MODE: 0 = dense, 1 = gather token (A row = code>>2), 2 = gather code
template <int MODE>
__global__ void __launch_bounds__(256, 2) gemm_mma(
    const float* __restrict__ Aext, int a_sel, int lda,
    const float* __restrict__ B1, const float* __restrict__ B2,
    int ldb, int nsplit,
    long bstride1, long bstride2,
    int c_sel, int ldc,
    int Ktot, int Mtot)
{
    __shared__ int codes[128];
    __shared__ __align__(16) char stage[2 * STAGE_B];   // 40 KB static

    const float* A = (a_sel < 0) ? Aext : buf_ptr(a_sel);
    float* C = buf_ptr(c_sel);

    int e = blockIdx.z;
    int row0 = blockIdx.y * 128;
    int cnt;
    const int* list = nullptr;
    if (MODE != 0) {
        cnt = g_counts[e];
        if (row0 >= cnt) return;
        list = g_list + e * TT;
    } else {
        cnt = Mtot;
        if (row0 >= cnt) return;
    }

    int tid = threadIdx.x;
    int wid = tid >> 5;
    int lane = tid & 31;

    if (tid < 128) {
        int r = row0 + tid;
        if (r >= cnt) r = cnt - 1;
        codes[tid] = (MODE != 0) ? list[r] : r;
    }
    __syncthreads();

    int n0 = blockIdx.x * 128;
    const float* B;
    if (n0 < nsplit) { B = B1 + (size_t)e * bstride1 + n0; }
    else             { B = B2 + (size_t)e * bstride2 + (n0 - nsplit); }

    // loader roles: BK = 32
    int arow_idx = tid >> 1, ak0 = (tid & 1) * 16;   // A: row, 16-float half of 32
    int a_src_row;
    {
        int code = codes[arow_idx];
        a_src_row = (MODE == 1) ? (code >> 2) : code;
    }
    const float* a_base = A + (size_t)a_src_row * lda + ak0;
    int bn = tid & 127, bk0 = (tid >> 7) * 16;       // B: col n, 16-k half of 32
    const float* b_base = B + bn + (size_t)bk0 * ldb;

    // compute roles
    int wm = (wid >> 2) * 64;
    int wn = (wid & 3) * 32;
    uint32_t sb = smem_u32(stage);
    int lrow = lane & 15, lkh = lane >> 4;
    int brow = lane & 7, bhalf = (lane >> 3) & 1;

    float c[4][4][4];
#pragma unroll
    for (int i = 0; i < 4; i++)
#pragma unroll
        for (int j = 0; j < 4; j++)
#pragma unroll
            for (int q = 0; q < 4; q++) c[i][j][q] = 0.f;

    int nt = Ktot >> 5;  // BK = 32

    uint32_t a_pk[8], b_pk[8];   // packed fp16 staging (16 elems each)

    __half* sA = (__half*)stage;
    __half* sB = (__half*)(stage + TILE_B);

    auto load_tile = [&](int t) {
        const float* ap = a_base + (t << 5);
#pragma unroll
        for (int j = 0; j < 4; j++) {
            float4 v = *(const float4*)(ap + j * 4);
            a_pk[j * 2 + 0] = packh2(v.x, v.y);
            a_pk[j * 2 + 1] = packh2(v.z, v.w);
        }
        const float* bp = b_base + (size_t)(t << 5) * ldb;
        float bv[16];
#pragma unroll
        for (int kk = 0; kk < 16; kk++) bv[kk] = bp[(size_t)kk * ldb];
#pragma unroll
        for (int j = 0; j < 8; j++) b_pk[j] = packh2(bv[2 * j], bv[2 * j + 1]);
    };
    auto store_tile = [&](int s) {
        __half* pA = sA + (size_t)s * (STAGE_B / 2);   // element arithmetic: full stage
        __half* pB = sB + (size_t)s * (STAGE_B / 2);
        int offA = arow_idx * RSTRIDE + ak0;
        *(uint4*)(pA + offA)     = make_uint4(a_pk[0], a_pk[1], a_pk[2], a_pk[3]);
        *(uint4*)(pA + offA + 8) = make_uint4(a_pk[4], a_pk[5], a_pk[6], a_pk[7]);
        int offB = bn * RSTRIDE + bk0;
        *(uint4*)(pB + offB)     = make_uint4(b_pk[0], b_pk[1], b_pk[2], b_pk[3]);
        *(uint4*)(pB + offB + 8) = make_uint4(b_pk[4], b_pk[5], b_pk[6], b_pk[7]);
    };

    // ---- prologue ----
    load_tile(0);
    store_tile(0);
    if (nt > 1) load_tile(1);
    __syncthreads();

    for (int t = 0; t < nt; t++) {
        int s = t & 1;
        uint32_t stA = sb + (uint32_t)s * STAGE_B;      // byte offset: full stage
        uint32_t stB = stA + (uint32_t)TILE_B;

#pragma unroll
        for (int kt = 0; kt < 2; kt++) {
            uint32_t bfrag[4][2];
#pragma unroll
            for (int ni = 0; ni < 4; ni++) {
                uint32_t adr = stB + 2u * (uint32_t)((wn + ni * 8 + brow) * RSTRIDE + kt * 16 + bhalf * 8);
                ldsm2(bfrag[ni], adr);
            }
#pragma unroll
            for (int mi = 0; mi < 4; mi++) {
                uint32_t afrag[4];
                uint32_t adr = stA + 2u * (uint32_t)((wm + mi * 16 + lrow) * RSTRIDE + kt * 16 + lkh * 8);
                ldsm4(afrag, adr);
#pragma unroll
                for (int ni = 0; ni < 4; ni++) {
                    mma16816(c[mi][ni], afrag, bfrag[ni]);
                }
            }
        }

        if (t + 1 < nt) store_tile(1 - s);
        if (t + 2 < nt) load_tile(t + 2);
        __syncthreads();
    }

    // ---- epilogue ----
    int g = lane >> 2, tig = lane & 3;
#pragma unroll
    for (int mi = 0; mi < 4; mi++) {
        int m1 = wm + mi * 16 + g;
        int m2 = m1 + 8;
        bool v1 = (row0 + m1) < cnt;
        bool v2 = (row0 + m2) < cnt;
        int cr1 = codes[m1], cr2 = codes[m2];
        float* p1 = C + (size_t)cr1 * ldc + n0 + wn + tig * 2;
        float* p2 = C + (size_t)cr2 * ldc + n0 + wn + tig * 2;
#pragma unroll
        for (int ni = 0; ni < 4; ni++) {
            if (v1) *(float2*)(p1 + ni * 8) = make_float2(c[mi][ni][0], c[mi][ni][1]);
            if (v2) *(float2*)(p2 + ni * 8) = make_float2(c[mi][ni][2], c[mi][ni][3]);
        }
    }
}

// ---------------- router ----------------
__global__ void zero_counts_kernel() {
    if (threadIdx.x < EE) g_counts[threadIdx.x] = 0;
}

__global__ void router_kernel(const float* __restrict__ x, const float* __restrict__ gw) {
    int t = blockIdx.x * 4 + (threadIdx.x >> 5);
    int lane = threadIdx.x & 31;
    if (t >= TT) return;
    float acc[EE];
#pragma unroll
    for (int e = 0; e < EE; e++) acc[e] = 0.f;
    const float* xr = x + (size_t)t * HH;
    for (int h = lane; h < HH; h += 32) {
        float xv = xr[h];
#pragma unroll
        for (int e = 0; e < EE; e++) acc[e] += xv * gw[e * HH + h];
    }
#pragma unroll
    for (int e = 0; e < EE; e++) {
#pragma unroll
        for (int o = 16; o > 0; o >>= 1) acc[e] += __shfl_xor_sync(0xffffffffu, acc[e], o);
    }
    if (lane == 0) {
        float m = acc[0];
#pragma unroll
        for (int e = 1; e < EE; e++) m = fmaxf(m, acc[e]);
        float sc[EE];
        float sum = 0.f;
#pragma unroll
        for (int e = 0; e < EE; e++) { sc[e] = expf(acc[e] - m); sum += sc[e]; }
        float inv = 1.f / sum;
#pragma unroll
        for (int e = 0; e < EE; e++) sc[e] *= inv;
        int idx[KTOP]; float w[KTOP]; float wsum = 0.f;
#pragma unroll
        for (int k = 0; k < KTOP; k++) {
            int bi = 0; float bv = -1.f;
#pragma unroll
            for (int e = 0; e < EE; e++) if (sc[e] > bv) { bv = sc[e]; bi = e; }
            idx[k] = bi; w[k] = bv; sc[bi] = -2.f; wsum += bv;
        }
        float winv = 1.f / wsum;
        for (int k = 0; k < KTOP; k++) {
            int code = t * KTOP + k;
            g_tw[code] = w[k] * winv;
            int pos = atomicAdd(&g_counts[idx[k]], 1);
            g_list[idx[k] * TT + pos] = code;
        }
    }
}

// ---------------- elementwise ----------------
__global__ void act_routed_kernel() {
    int v = blockIdx.x * blockDim.x + threadIdx.x;
    const int per = II / 4;
    if (v >= TT * KTOP * per) return;
    int code = v / per, c4 = v - code * per;
    const float* row = g_gu + (size_t)code * (2 * II);
    float4 g4 = *(const float4*)(row + c4 * 4);
    float4 u4 = *(const float4*)(row + II + c4 * 4);
    float w = g_tw[code];
    float4 o;
    o.x = (g4.x / (1.f + __expf(-g4.x))) * u4.x * w;
    o.y = (g4.y / (1.f + __expf(-g4.y))) * u4.y * w;
    o.z = (g4.z / (1.f + __expf(-g4.z))) * u4.z * w;
    o.w = (g4.w / (1.f + __expf(-g4.w))) * u4.w * w;
    *(float4*)(g_act + (size_t)code * II + c4 * 4) = o;
}

__global__ void act_shared_kernel() {
    int v = blockIdx.x * blockDim.x + threadIdx.x;
    const int per = ISH / 4;
    if (v >= TT * per) return;
    int t = v / per, c4 = v - t * per;
    const float* row = g_sgu + (size_t)t * (2 * ISH);
    float4 g4 = *(const float4*)(row + c4 * 4);
    float4 u4 = *(const float4*)(row + ISH + c4 * 4);
    float4 o;
    o.x = (g4.x / (1.f + __expf(-g4.x))) * u4.x;
    o.y = (g4.y / (1.f + __expf(-g4.y))) * u4.y;
    o.z = (g4.z / (1.f + __expf(-g4.z))) * u4.z;
    o.w = (g4.w / (1.f + __expf(-g4.w))) * u4.w;
    *(float4*)(g_shact + (size_t)t * ISH + c4 * 4) = o;
}

__global__ void combine_kernel(float* __restrict__ out) {
    int v = blockIdx.x * blockDim.x + threadIdx.x;
    const int per = HH / 4;
    if (v >= TT * per) return;
    int t = v / per, h4 = v - t * per;
    float4 acc = *(const float4*)(g_shdown + (size_t)t * HH + h4 * 4);
#pragma unroll
    for (int k = 0; k < KTOP; k++) {
        float4 d = *(const float4*)(g_downbuf + (size_t)(t * KTOP + k) * HH + h4 * 4);
        acc.x += d.x; acc.y += d.y; acc.z += d.z; acc.w += d.w;
    }
    *(float4*)(out + (size_t)t * HH + h4 * 4) = acc;
}

// ---------------- launch ----------------
extern "C" void kernel_launch(void* const* d_in, const int* in_sizes, int n_in,
                              void* d_out, int out_size) {
    const float* x       = (const float*)d_in[0];
    const float* gate_w  = (const float*)d_in[1];
    const float* w_gate  = (const float*)d_in[2];
    const float* w_up    = (const float*)d_in[3];
    const float* w_down  = (const float*)d_in[4];
    const float* sw_gate = (const float*)d_in[5];
    const float* sw_up   = (const float*)d_in[6];
    const float* sw_down = (const float*)d_in[7];
    float* out = (float*)d_out;

    zero_counts_kernel<<<1, 32>>>();
    router_kernel<<<TT / 4, 128>>>(x, gate_w);

    gemm_mma<1><<<dim3(2 * II / 128, TT / 128, EE), 256>>>(
        x, -1, HH, w_gate, w_up, II, II,
        (long)HH * II, (long)HH * II, 0, 2 * II, HH, 0);

    act_routed_kernel<<<(TT * KTOP * (II / 4) + 255) / 256, 256>>>();

    gemm_mma<2><<<dim3(HH / 128, TT / 128, EE), 256>>>(
        nullptr, 1, II, w_down, w_down, HH, HH,
        (long)II * HH, 0, 2, HH, II, 0);

    gemm_mma<0><<<dim3(2 * ISH / 128, TT / 128, 1), 256>>>(
        x, -1, HH, sw_gate, sw_up, ISH, ISH,
        0, 0, 3, 2 * ISH, HH, TT);

    act_shared_kernel<<<(TT * (ISH / 4) + 255) / 256, 256>>>();

    gemm_mma<0><<<dim3(HH / 128, TT / 128, 1), 256>>>(
        nullptr, 4, ISH, sw_down, sw_down, HH, HH,
        0, 0, 5, HH, ISH, TT);

    combine_kernel<<<(TT * (HH / 4) + 255) / 256, 256>>>(out);
}